// round 16
// baseline (speedup 1.0000x reference)
#include <cuda_runtime.h>
#include <cuda_fp16.h>
#include <cstdint>

// Problem constants
#define BATCH 32
#define CCH   2048
#define HW    1024
#define MID   128

// Scratch (allocation-free rule: __device__ globals)
static __device__ float    g_P[(long)BATCH * HW * HW];                 // 128 MB
static __device__ __half   g_camH[(long)BATCH * CCH * HW];             // 128 MB (superchunk-32 fp16)
static __device__ uint32_t g_Wpk[128 * 4096];                          // 2 MB
static __device__ uint32_t g_featPk[(long)BATCH * 128 * HW * 16];      // 256 MB
static __device__ uint32_t g_f12pk[(long)BATCH * 16 * HW * 16];        // 32 MB

// ===========================================================================
// Helpers
// ===========================================================================
__device__ __forceinline__ uint32_t smem_u32(const void* p) {
    uint32_t a;
    asm("{ .reg .u64 t; cvta.to.shared.u64 t, %1; cvt.u32.u64 %0, t; }" : "=r"(a) : "l"(p));
    return a;
}
__device__ __forceinline__ void mma_f16(float* c, uint32_t a0, uint32_t a1, uint32_t a2, uint32_t a3,
                                        uint32_t b0, uint32_t b1) {
    asm volatile(
        "mma.sync.aligned.m16n8k16.row.col.f32.f16.f16.f32 "
        "{%0,%1,%2,%3}, {%4,%5,%6,%7}, {%8,%9}, {%0,%1,%2,%3};"
        : "+f"(c[0]), "+f"(c[1]), "+f"(c[2]), "+f"(c[3])
        : "r"(a0), "r"(a1), "r"(a2), "r"(a3), "r"(b0), "r"(b1));
}
__device__ __forceinline__ void mma_bf16(float* c, const uint32_t* a, uint32_t b0, uint32_t b1) {
    asm volatile(
        "mma.sync.aligned.m16n8k16.row.col.f32.bf16.bf16.f32 "
        "{%0,%1,%2,%3}, {%4,%5,%6,%7}, {%8,%9}, {%0,%1,%2,%3};"
        : "+f"(c[0]), "+f"(c[1]), "+f"(c[2]), "+f"(c[3])
        : "r"(a[0]), "r"(a[1]), "r"(a[2]), "r"(a[3]), "r"(b0), "r"(b1));
}
__device__ __forceinline__ uint32_t bf16x2_pack(float e, float o) {
    uint32_t r;
    asm("cvt.rn.bf16x2.f32 %0, %1, %2;" : "=r"(r) : "f"(o), "f"(e));
    return r;
}
__device__ __forceinline__ uint32_t bf16x2_residual(float e, float o, uint32_t hi) {
    const float he = __uint_as_float(hi << 16);
    const float ho = __uint_as_float(hi & 0xffff0000u);
    return bf16x2_pack(e - he, o - ho);
}
#define CP_ASYNC16(smem_addr, gptr) \
    asm volatile("cp.async.cg.shared.global [%0], [%1], 16;" :: "r"(smem_addr), "l"(gptr))
#define CP_COMMIT() asm volatile("cp.async.commit_group;" ::: "memory")
#define CP_WAIT2()  asm volatile("cp.async.wait_group 2;"  ::: "memory")

// Quad packed format (bf16 split GEMMs), per 16-k chunk, per row (64B):
//   uint32 index 4u = hi[u] (u<4), 4u+1 = hi[u+4], 4u+2 = lo[u], 4u+3 = lo[u+4].
// fp16 16-chunk format (P rows, GEMM3 B): pair u at slot (u&3)*2 + (u>>2).
// fp16 superchunk-32 format (camH): per 64B block, pair p at word (p&3)*4+(p>>2).

// ===========================================================================
// prep_w: Wq/Wk [128][2048] -> quad-packed [128 chunks][256 rows][16]
// ===========================================================================
__global__ void __launch_bounds__(256)
prep_w_kernel(const float* __restrict__ Wq, const float* __restrict__ Wk,
              uint32_t* __restrict__ Wpk)
{
    const int idx = blockIdx.x * 256 + threadIdx.x;
    const int m = idx >> 7;
    const int c = idx & 127;
    const float* src = (m < 128 ? Wq + (long)m * CCH : Wk + (long)(m - 128) * CCH) + c * 16;

    float f[16];
#pragma unroll
    for (int q = 0; q < 4; q++)
        *reinterpret_cast<float4*>(f + q * 4) = *reinterpret_cast<const float4*>(src + q * 4);

    uint32_t hi[8], lo[8];
#pragma unroll
    for (int u = 0; u < 8; u++) {
        hi[u] = bf16x2_pack(f[2 * u], f[2 * u + 1]);
        lo[u] = bf16x2_residual(f[2 * u], f[2 * u + 1], hi[u]);
    }
    uint4* d = reinterpret_cast<uint4*>(Wpk + (long)c * 4096 + m * 16);
#pragma unroll
    for (int t = 0; t < 4; t++)
        d[t] = make_uint4(hi[t], hi[t + 4], lo[t], lo[t + 4]);
}

// ===========================================================================
// pack_rows: [C][n] fp32 -> quad-packed (pairs across first dim) — feat only
// ===========================================================================
__global__ void __launch_bounds__(256)
pack_rows_kernel(const float* __restrict__ src, uint32_t* __restrict__ dst,
                 int chunks)
{
    const long idx = (long)blockIdx.x * 256 + threadIdx.x;
    const int  n   = (int)(idx & (HW - 1));
    const long bc  = idx >> 10;
    const int  c   = (int)(bc % chunks);
    const long b   = bc / chunks;

    const float* s = src + (b * chunks + c) * 16 * (long)HW + n;
    float f[16];
#pragma unroll
    for (int j = 0; j < 16; j++) f[j] = s[(long)j * HW];

    uint32_t hi[8], lo[8];
#pragma unroll
    for (int u = 0; u < 8; u++) {
        hi[u] = bf16x2_pack(f[2 * u], f[2 * u + 1]);
        lo[u] = bf16x2_residual(f[2 * u], f[2 * u + 1], hi[u]);
    }
    uint4* base = reinterpret_cast<uint4*>(dst + (b * chunks + c) * (long)(HW * 16) + n * 16);
#pragma unroll
    for (int t = 0; t < 4; t++)
        base[t] = make_uint4(hi[t], hi[t + 4], lo[t], lo[t + 4]);
}

// ===========================================================================
// prep_cam: camH = superchunk-32 fp16 copy of cam
// ===========================================================================
__global__ void __launch_bounds__(256)
prep_cam_kernel(const float* __restrict__ cam, __half* __restrict__ camH)
{
    const long i4 = (long)blockIdx.x * blockDim.x + threadIdx.x;
    const float4 v = reinterpret_cast<const float4*>(cam)[i4];
    const long row  = i4 >> 8;
    const int  idx4 = (int)(i4 & 255);
    const int  sc   = idx4 >> 3;
    const int  j    = idx4 & 7;
    const int p0 = 2 * j, p1 = 2 * j + 1;
    const int w0 = (p0 & 3) * 4 + (p0 >> 2);
    const int w1 = (p1 & 3) * 4 + (p1 >> 2);
    __half2* base = reinterpret_cast<__half2*>(camH + row * HW + sc * 32);
    base[w0] = __floats2half2_rn(v.x, v.y);
    base[w1] = __floats2half2_rn(v.z, v.w);
}

// ===========================================================================
// Softmax: fp32 row of 1024 -> fp16 16-chunk permuted, in-place (__expf)
// ===========================================================================
__global__ void __launch_bounds__(256)
softmax_kernel(float* __restrict__ P)
{
    __shared__ float red_m[8];
    __shared__ float red_s[8];

    const long row = blockIdx.x;
    float* rowp = P + row * (long)HW;
    const float4 v = reinterpret_cast<const float4*>(rowp)[threadIdx.x];

    const int lane = threadIdx.x & 31;
    const int warp = threadIdx.x >> 5;

    float m = fmaxf(fmaxf(v.x, v.y), fmaxf(v.z, v.w));
#pragma unroll
    for (int o = 16; o; o >>= 1) m = fmaxf(m, __shfl_xor_sync(0xffffffffu, m, o));
    if (lane == 0) red_m[warp] = m;
    __syncthreads();
    m = red_m[0];
#pragma unroll
    for (int i = 1; i < 8; i++) m = fmaxf(m, red_m[i]);

    float4 e;
    e.x = __expf(v.x - m);
    e.y = __expf(v.y - m);
    e.z = __expf(v.z - m);
    e.w = __expf(v.w - m);
    float s = e.x + e.y + e.z + e.w;
#pragma unroll
    for (int o = 16; o; o >>= 1) s += __shfl_xor_sync(0xffffffffu, s, o);
    if (lane == 0) red_s[warp] = s;
    __syncthreads();
    s = red_s[0];
#pragma unroll
    for (int i = 1; i < 8; i++) s += red_s[i];

    const float inv = 1.0f / s;
    const int chunk = threadIdx.x >> 2;
    const int j     = threadIdx.x & 3;
    const int slotA = ((2 * j) & 3) * 2 + ((2 * j) >> 2);
    const int slotB = ((2 * j + 1) & 3) * 2 + ((2 * j + 1) >> 2);
    __half2* base = reinterpret_cast<__half2*>(reinterpret_cast<__half*>(rowp) + chunk * 16);
    base[slotA] = __floats2half2_rn(e.x * inv, e.y * inv);
    base[slotB] = __floats2half2_rn(e.z * inv, e.w * inv);
}

// ===========================================================================
// Quad-packed 3xbf16 GEMM.
//   ASTREAM=false (GEMM1): A staged in smem (stage = A 8KB + B 8KB).
//   ASTREAM=true  (GEMM2): A frags via __ldg from gmem (L2-resident, reused
//                          by 8 n-CTAs); smem stages B only (8KB/stage).
//   PACKOUT=true  (GEMM1): epilogue emits quad-packed bf16 hi/lo.
// Single barrier per iteration (bottom barrier provably redundant at 4 stages).
// ===========================================================================
#define T2_STAGES 4
#define T2_SMEM_FULL (T2_STAGES * 4096 * 4)   // 65536 (A+B staging)
#define T2_SMEM_BONLY (T2_STAGES * 2048 * 4)  // 32768 (B only)

template<int KCHUNKS, int CSA, int CSB, bool PACKOUT, bool ASTREAM>
__global__ void __launch_bounds__(256, 2)
pk_gemm_kernel(const uint32_t* __restrict__ Apk, const uint32_t* __restrict__ Bpk,
               float* __restrict__ Cg,
               long bsA, long bsB, long bsC)
{
    extern __shared__ uint32_t smu[];
    constexpr int STAGEU = ASTREAM ? 2048 : 4096;

    const int tid  = threadIdx.x;
    const int wid  = tid >> 5;
    const int lane = tid & 31;
    const int g    = lane >> 2;
    const int t    = lane & 3;
    const int wm   = wid >> 1;
    const int wn   = wid & 1;

    const int b  = blockIdx.z;
    const int m0 = blockIdx.y * 128;
    const int n0 = blockIdx.x * 128;

    const uint32_t sm_u = smem_u32(smu);

    // B staging descriptors
    uint32_t sOffB[2];
    const uint32_t* bPtr[2];
    // A staging (ASTREAM=false)
    uint32_t sOffA[2];
    const uint32_t* aPtr[2];
#pragma unroll
    for (int i = 0; i < 2; i++) {
        const int cid = tid + i * 256;
        const int row = cid >> 2, q = cid & 3;
        const uint32_t off = (uint32_t)(row * 16 + q * 4) * 4u;
        if (ASTREAM) {
            sOffB[i] = off;
        } else {
            sOffA[i] = off;
            sOffB[i] = off + 2048u * 4u;
            aPtr[i] = Apk + b * bsA + (long)(m0 + row) * 16 + q * 4;
        }
        bPtr[i] = Bpk + b * bsB + (long)(n0 + row) * 16 + q * 4;
    }

    // A direct-ldg row pointers (ASTREAM=true): [mt][row-half]
    const uint32_t* aFrag[2][2];
    if (ASTREAM) {
#pragma unroll
        for (int mt = 0; mt < 2; mt++)
#pragma unroll
            for (int r = 0; r < 2; r++)
                aFrag[mt][r] = Apk + b * bsA
                             + (long)(m0 + wm * 32 + mt * 16 + r * 8 + g) * 16 + t * 4;
    }

    float acc[2][8][4];
#pragma unroll
    for (int i = 0; i < 2; i++)
#pragma unroll
        for (int j = 0; j < 8; j++)
#pragma unroll
            for (int k = 0; k < 4; k++) acc[i][j][k] = 0.f;

    auto load_stage = [&](int s) {
        const uint32_t sa = sm_u + (uint32_t)(s * STAGEU) * 4u;
        if (!ASTREAM) {
#pragma unroll
            for (int i = 0; i < 2; i++) {
                CP_ASYNC16(sa + sOffA[i], aPtr[i]);
                aPtr[i] += CSA;
            }
        }
#pragma unroll
        for (int i = 0; i < 2; i++) {
            CP_ASYNC16(sa + sOffB[i], bPtr[i]);
            bPtr[i] += CSB;
        }
    };

#pragma unroll
    for (int s = 0; s < T2_STAGES - 1; s++) {
        load_stage(s);
        CP_COMMIT();
    }

    for (int it = 0; it < KCHUNKS; it++) {
        CP_WAIT2();
        __syncthreads();
        if (it + T2_STAGES - 1 < KCHUNKS)
            load_stage((it + T2_STAGES - 1) & (T2_STAGES - 1));
        CP_COMMIT();

        const int s = it & (T2_STAGES - 1);
        const uint32_t* sbase = smu + s * STAGEU;
        const uint32_t* sb = ASTREAM ? sbase : sbase + 2048;

        uint32_t ahi[2][4], alo[2][4];
        if (ASTREAM) {
#pragma unroll
            for (int mt = 0; mt < 2; mt++) {
                const uint4 v0 = __ldg(reinterpret_cast<const uint4*>(aFrag[mt][0] + (long)it * CSA));
                const uint4 v1 = __ldg(reinterpret_cast<const uint4*>(aFrag[mt][1] + (long)it * CSA));
                ahi[mt][0] = v0.x; ahi[mt][1] = v1.x; ahi[mt][2] = v0.y; ahi[mt][3] = v1.y;
                alo[mt][0] = v0.z; alo[mt][1] = v1.z; alo[mt][2] = v0.w; alo[mt][3] = v1.w;
            }
        } else {
            const uint32_t* sa = sbase;
#pragma unroll
            for (int mt = 0; mt < 2; mt++) {
                const int r0 = wm * 32 + mt * 16 + g;
                const uint4 v0 = *reinterpret_cast<const uint4*>(sa + r0 * 16 + t * 4);
                const uint4 v1 = *reinterpret_cast<const uint4*>(sa + (r0 + 8) * 16 + t * 4);
                ahi[mt][0] = v0.x; ahi[mt][1] = v1.x; ahi[mt][2] = v0.y; ahi[mt][3] = v1.y;
                alo[mt][0] = v0.z; alo[mt][1] = v1.z; alo[mt][2] = v0.w; alo[mt][3] = v1.w;
            }
        }

#pragma unroll
        for (int nt = 0; nt < 8; nt++) {
            const int n = wn * 64 + nt * 8 + g;
            const uint4 u = *reinterpret_cast<const uint4*>(sb + n * 16 + t * 4);
#pragma unroll
            for (int mt = 0; mt < 2; mt++) {
                mma_bf16(acc[mt][nt], ahi[mt], u.x, u.y);
                mma_bf16(acc[mt][nt], ahi[mt], u.z, u.w);
                mma_bf16(acc[mt][nt], alo[mt], u.x, u.y);
            }
        }
        // bottom barrier removed: next iteration's top barrier orders the
        // stage rewrite (prefetch distance 3 == last-read distance 1 mod 4).
    }

    if (PACKOUT) {
        uint32_t* Cpk = reinterpret_cast<uint32_t*>(Cg) + (long)b * bsC;
        const bool evn = (g & 1) == 0;
        const int  u   = g >> 1;
#pragma unroll
        for (int mt = 0; mt < 2; mt++) {
            const int chunk = (m0 >> 4) + wm * 2 + mt;
            uint32_t* dstC = Cpk + (long)chunk * (HW * 16);
#pragma unroll
            for (int nt = 0; nt < 8; nt++) {
                const int n = n0 + wn * 64 + nt * 8 + 2 * t;
                float v0 = acc[mt][nt][0], v1 = acc[mt][nt][1];
                float v2 = acc[mt][nt][2], v3 = acc[mt][nt][3];
                const float p0 = __shfl_xor_sync(0xffffffffu, v0, 4);
                const float p1 = __shfl_xor_sync(0xffffffffu, v1, 4);
                const float p2 = __shfl_xor_sync(0xffffffffu, v2, 4);
                const float p3 = __shfl_xor_sync(0xffffffffu, v3, 4);
                if (evn) {
                    uint2 w0, w1;
                    w0.x = bf16x2_pack(v0, p0);  w0.y = bf16x2_pack(v2, p2);
                    w1.x = bf16x2_pack(v1, p1);  w1.y = bf16x2_pack(v3, p3);
                    *reinterpret_cast<uint2*>(dstC + (long)n * 16 + u * 4) = w0;
                    *reinterpret_cast<uint2*>(dstC + (long)(n + 1) * 16 + u * 4) = w1;
                } else {
                    uint32_t h, l0, l2, l1, l3;
                    h = bf16x2_pack(p0, v0); l0 = bf16x2_residual(p0, v0, h);
                    h = bf16x2_pack(p2, v2); l2 = bf16x2_residual(p2, v2, h);
                    h = bf16x2_pack(p1, v1); l1 = bf16x2_residual(p1, v1, h);
                    h = bf16x2_pack(p3, v3); l3 = bf16x2_residual(p3, v3, h);
                    uint2 w0 = make_uint2(l0, l2);
                    uint2 w1 = make_uint2(l1, l3);
                    *reinterpret_cast<uint2*>(dstC + (long)n * 16 + u * 4 + 2) = w0;
                    *reinterpret_cast<uint2*>(dstC + (long)(n + 1) * 16 + u * 4 + 2) = w1;
                }
            }
        }
    } else {
        float* C = Cg + (long)b * bsC;
#pragma unroll
        for (int mt = 0; mt < 2; mt++) {
            const int mrow = m0 + wm * 32 + mt * 16 + g;
#pragma unroll
            for (int nt = 0; nt < 8; nt++) {
                const int n = n0 + wn * 64 + nt * 8 + 2 * t;
                *(float2*)(C + (long)mrow * HW + n) = make_float2(acc[mt][nt][0], acc[mt][nt][1]);
                *(float2*)(C + (long)(mrow + 8) * HW + n) = make_float2(acc[mt][nt][2], acc[mt][nt][3]);
            }
        }
    }
}

// ===========================================================================
// GEMM3 (fp16 m16n8k16): A (camH superchunk) streamed via LDG.128 + prefetch;
// smem stages B only. Single barrier per iteration.
// ===========================================================================
#define G3_STAGES 4
#define G3_CHUNK_BYTES 4096
#define G3_STAGE_BYTES (2 * G3_CHUNK_BYTES)
#define G3_SMEM_BYTES  (G3_STAGES * G3_STAGE_BYTES)   // 32768
#define G3_SCITER (HW / 32)

__global__ void __launch_bounds__(256, 2)
gemm3_f16_kernel(const __half* __restrict__ camH,
                 const float* __restrict__ Pf,
                 float* __restrict__ out, const float* __restrict__ alphap)
{
    extern __shared__ char smc[];

    const int tid  = threadIdx.x;
    const int wid  = tid >> 5;
    const int lane = tid & 31;
    const int g    = lane >> 2;
    const int t    = lane & 3;
    const int wm   = wid >> 1;
    const int wn   = wid & 1;

    const int b  = blockIdx.z;
    const int m0 = blockIdx.y * 128;
    const int n0 = blockIdx.x * 128;
    const __half* camHB = camH + (long)b * CCH * HW;

    const uint32_t sm_u = smem_u32(smc);

    uint32_t sOff[2];
    const __half* bPtr[2];
    {
        const __half* PBh = reinterpret_cast<const __half*>(Pf + (long)b * HW * HW);
#pragma unroll
        for (int i = 0; i < 2; i++) {
            const int c = tid + i * 256;
            const int row = c >> 2, q = c & 3;
            sOff[i] = (uint32_t)((q >> 1) * G3_CHUNK_BYTES + row * 32 + (q & 1) * 16);
            bPtr[i] = PBh + (long)(n0 + row) * 2048 + q * 8;
        }
    }

    const __half* aRow[2][2];
#pragma unroll
    for (int mt = 0; mt < 2; mt++)
#pragma unroll
        for (int r = 0; r < 2; r++)
            aRow[mt][r] = camHB + (long)(m0 + wm * 32 + mt * 16 + r * 8 + g) * HW + t * 8;

    float acc[2][8][4];
#pragma unroll
    for (int i = 0; i < 2; i++)
#pragma unroll
        for (int j = 0; j < 8; j++)
#pragma unroll
            for (int k = 0; k < 4; k++) acc[i][j][k] = 0.f;

    auto load_stage = [&](int s) {
        const uint32_t sb = sm_u + (uint32_t)(s * G3_STAGE_BYTES);
#pragma unroll
        for (int i = 0; i < 2; i++) {
            CP_ASYNC16(sb + sOff[i], bPtr[i]);
            bPtr[i] += 32;
        }
    };

#pragma unroll
    for (int s = 0; s < G3_STAGES - 1; s++) {
        load_stage(s);
        CP_COMMIT();
    }

    uint4 aC[2][2], aN[2][2];
#pragma unroll
    for (int mt = 0; mt < 2; mt++)
#pragma unroll
        for (int r = 0; r < 2; r++)
            aC[mt][r] = __ldg(reinterpret_cast<const uint4*>(aRow[mt][r]));

    for (int it = 0; it < G3_SCITER; it++) {
        CP_WAIT2();
        __syncthreads();
        if (it + G3_STAGES - 1 < G3_SCITER)
            load_stage((it + G3_STAGES - 1) & (G3_STAGES - 1));
        CP_COMMIT();

        if (it + 1 < G3_SCITER) {
#pragma unroll
            for (int mt = 0; mt < 2; mt++)
#pragma unroll
                for (int r = 0; r < 2; r++)
                    aN[mt][r] = __ldg(reinterpret_cast<const uint4*>(aRow[mt][r] + (it + 1) * 32));
        }

        const int s = it & (G3_STAGES - 1);
        const char* sb = smc + s * G3_STAGE_BYTES;

#pragma unroll
        for (int ch = 0; ch < 2; ch++) {
            const char* sbc = sb + ch * G3_CHUNK_BYTES;
            uint32_t a0[2], a1[2], a2[2], a3[2];
#pragma unroll
            for (int mt = 0; mt < 2; mt++) {
                if (ch == 0) {
                    a0[mt] = aC[mt][0].x; a1[mt] = aC[mt][1].x;
                    a2[mt] = aC[mt][0].y; a3[mt] = aC[mt][1].y;
                } else {
                    a0[mt] = aC[mt][0].z; a1[mt] = aC[mt][1].z;
                    a2[mt] = aC[mt][0].w; a3[mt] = aC[mt][1].w;
                }
            }
#pragma unroll
            for (int nt = 0; nt < 8; nt++) {
                const int n = wn * 64 + nt * 8 + g;
                const uint2 bf = *reinterpret_cast<const uint2*>(sbc + n * 32 + t * 8);
#pragma unroll
                for (int mt = 0; mt < 2; mt++)
                    mma_f16(acc[mt][nt], a0[mt], a1[mt], a2[mt], a3[mt], bf.x, bf.y);
            }
        }

#pragma unroll
        for (int mt = 0; mt < 2; mt++)
#pragma unroll
            for (int r = 0; r < 2; r++)
                aC[mt][r] = aN[mt][r];
        // bottom barrier removed (same prefetch-distance argument as pk_gemm)
    }

    const float alpha = *alphap;
    float* outB = out + (long)b * CCH * HW;
#pragma unroll
    for (int mt = 0; mt < 2; mt++) {
        const int mrow = m0 + wm * 32 + mt * 16 + g;
        const __half* camRow0 = camHB + (long)mrow * HW;
        const __half* camRow1 = camHB + (long)(mrow + 8) * HW;
#pragma unroll
        for (int nt = 0; nt < 8; nt++) {
            const int n = n0 + wn * 64 + nt * 8 + 2 * t;
            const int p = (n >> 1) & 15;
            const int off = (n & ~31) + ((p & 3) * 4 + (p >> 2)) * 2;
            {
                const float2 cv = __half22float2(*reinterpret_cast<const __half2*>(camRow0 + off));
                float2 o;
                o.x = alpha * acc[mt][nt][0] + cv.x;
                o.y = alpha * acc[mt][nt][1] + cv.y;
                *(float2*)(outB + (long)mrow * HW + n) = o;
            }
            {
                const float2 cv = __half22float2(*reinterpret_cast<const __half2*>(camRow1 + off));
                float2 o;
                o.x = alpha * acc[mt][nt][2] + cv.x;
                o.y = alpha * acc[mt][nt][3] + cv.y;
                *(float2*)(outB + (long)(mrow + 8) * HW + n) = o;
            }
        }
    }
}

// ---------------------------------------------------------------------------
extern "C" void kernel_launch(void* const* d_in, const int* in_sizes, int n_in,
                              void* d_out, int out_size)
{
    const float* feat  = (const float*)d_in[0];
    const float* cam   = (const float*)d_in[1];
    const float* Wq    = (const float*)d_in[2];
    const float* Wk    = (const float*)d_in[3];
    const float* alpha = (const float*)d_in[4];
    float* out = (float*)d_out;

    float* P;
    __half* camH;
    uint32_t *Wpk, *featPk, *f12pk;
    cudaGetSymbolAddress((void**)&P, g_P);
    cudaGetSymbolAddress((void**)&camH, g_camH);
    cudaGetSymbolAddress((void**)&Wpk, g_Wpk);
    cudaGetSymbolAddress((void**)&featPk, g_featPk);
    cudaGetSymbolAddress((void**)&f12pk, g_f12pk);

    // Preps
    prep_w_kernel<<<128, 256>>>(Wq, Wk, Wpk);
    pack_rows_kernel<<<(unsigned)((long)BATCH * 128 * HW / 256), 256>>>(feat, featPk, 128);
    prep_cam_kernel<<<(unsigned)((long)BATCH * CCH * HW / 4 / 256), 256>>>(cam, camH);

    // GEMM1 (A smem, PACKOUT): f12pk = quad-packed W @ feat
    {
        cudaFuncSetAttribute((const void*)pk_gemm_kernel<128, 4096, 16384, true, false>,
                             cudaFuncAttributeMaxDynamicSharedMemorySize, T2_SMEM_FULL);
        dim3 grid(HW / 128, 256 / 128, BATCH);
        pk_gemm_kernel<128, 4096, 16384, true, false><<<grid, 256, T2_SMEM_FULL>>>(
            Wpk, featPk, (float*)f12pk,
            0L, (long)128 * HW * 16, (long)16 * HW * 16);
    }

    // GEMM2 (A streamed from gmem, B-only smem): S = f1^T f2 (8 chunks)
    {
        cudaFuncSetAttribute((const void*)pk_gemm_kernel<8, 16384, 16384, false, true>,
                             cudaFuncAttributeMaxDynamicSharedMemorySize, T2_SMEM_BONLY);
        dim3 grid(HW / 128, HW / 128, BATCH);
        pk_gemm_kernel<8, 16384, 16384, false, true><<<grid, 256, T2_SMEM_BONLY>>>(
            f12pk, f12pk + (long)8 * HW * 16, P,
            (long)16 * HW * 16, (long)16 * HW * 16, (long)HW * HW);
    }

    // Softmax (fp32 -> 16-chunk fp16, in-place)
    softmax_kernel<<<BATCH * HW, 256>>>(P);

    // GEMM3: out = alpha * cam @ P^T + cam
    {
        cudaFuncSetAttribute(gemm3_f16_kernel,
                             cudaFuncAttributeMaxDynamicSharedMemorySize, G3_SMEM_BYTES);
        dim3 grid(HW / 128, CCH / 128, BATCH);
        gemm3_f16_kernel<<<grid, 256, G3_SMEM_BYTES>>>(camH, P, out, alpha);
    }
}

// round 17
// speedup vs baseline: 1.0152x; 1.0152x over previous
#include <cuda_runtime.h>
#include <cuda_fp16.h>
#include <cstdint>

// Problem constants
#define BATCH 32
#define CCH   2048
#define HW    1024
#define MID   128

// Scratch (allocation-free rule: __device__ globals)
static __device__ float    g_P[(long)BATCH * HW * HW];                 // 128 MB
static __device__ __half   g_camH[(long)BATCH * CCH * HW];             // 128 MB (superchunk-32 fp16)
static __device__ uint32_t g_Wpk[128 * 4096];                          // 2 MB
static __device__ uint32_t g_featPk[(long)BATCH * 128 * HW * 16];      // 256 MB
static __device__ uint32_t g_f12pk[(long)BATCH * 16 * HW * 16];        // 32 MB

// ===========================================================================
// Helpers
// ===========================================================================
__device__ __forceinline__ uint32_t smem_u32(const void* p) {
    uint32_t a;
    asm("{ .reg .u64 t; cvta.to.shared.u64 t, %1; cvt.u32.u64 %0, t; }" : "=r"(a) : "l"(p));
    return a;
}
__device__ __forceinline__ void mma_f16(float* c, uint32_t a0, uint32_t a1, uint32_t a2, uint32_t a3,
                                        uint32_t b0, uint32_t b1) {
    asm volatile(
        "mma.sync.aligned.m16n8k16.row.col.f32.f16.f16.f32 "
        "{%0,%1,%2,%3}, {%4,%5,%6,%7}, {%8,%9}, {%0,%1,%2,%3};"
        : "+f"(c[0]), "+f"(c[1]), "+f"(c[2]), "+f"(c[3])
        : "r"(a0), "r"(a1), "r"(a2), "r"(a3), "r"(b0), "r"(b1));
}
__device__ __forceinline__ void mma_bf16(float* c, const uint32_t* a, uint32_t b0, uint32_t b1) {
    asm volatile(
        "mma.sync.aligned.m16n8k16.row.col.f32.bf16.bf16.f32 "
        "{%0,%1,%2,%3}, {%4,%5,%6,%7}, {%8,%9}, {%0,%1,%2,%3};"
        : "+f"(c[0]), "+f"(c[1]), "+f"(c[2]), "+f"(c[3])
        : "r"(a[0]), "r"(a[1]), "r"(a[2]), "r"(a[3]), "r"(b0), "r"(b1));
}
__device__ __forceinline__ uint32_t bf16x2_pack(float e, float o) {
    uint32_t r;
    asm("cvt.rn.bf16x2.f32 %0, %1, %2;" : "=r"(r) : "f"(o), "f"(e));
    return r;
}
__device__ __forceinline__ uint32_t bf16x2_residual(float e, float o, uint32_t hi) {
    const float he = __uint_as_float(hi << 16);
    const float ho = __uint_as_float(hi & 0xffff0000u);
    return bf16x2_pack(e - he, o - ho);
}
#define CP_ASYNC16(smem_addr, gptr) \
    asm volatile("cp.async.cg.shared.global [%0], [%1], 16;" :: "r"(smem_addr), "l"(gptr))
#define CP_COMMIT() asm volatile("cp.async.commit_group;" ::: "memory")
#define CP_WAIT2()  asm volatile("cp.async.wait_group 2;"  ::: "memory")

// Quad packed format (bf16 split GEMMs), per 16-k chunk, per row (64B):
//   uint32 index 4u = hi[u] (u<4), 4u+1 = hi[u+4], 4u+2 = lo[u], 4u+3 = lo[u+4].
// fp16 16-chunk format (P rows, GEMM3 B): pair u at slot (u&3)*2 + (u>>2).
// fp16 superchunk-32 format (camH): per 64B block, pair p at word (p&3)*4+(p>>2).

// ===========================================================================
// prep_w: Wq/Wk [128][2048] -> quad-packed [128 chunks][256 rows][16]
// ===========================================================================
__global__ void __launch_bounds__(256)
prep_w_kernel(const float* __restrict__ Wq, const float* __restrict__ Wk,
              uint32_t* __restrict__ Wpk)
{
    const int idx = blockIdx.x * 256 + threadIdx.x;
    const int m = idx >> 7;
    const int c = idx & 127;
    const float* src = (m < 128 ? Wq + (long)m * CCH : Wk + (long)(m - 128) * CCH) + c * 16;

    float f[16];
#pragma unroll
    for (int q = 0; q < 4; q++)
        *reinterpret_cast<float4*>(f + q * 4) = *reinterpret_cast<const float4*>(src + q * 4);

    uint32_t hi[8], lo[8];
#pragma unroll
    for (int u = 0; u < 8; u++) {
        hi[u] = bf16x2_pack(f[2 * u], f[2 * u + 1]);
        lo[u] = bf16x2_residual(f[2 * u], f[2 * u + 1], hi[u]);
    }
    uint4* d = reinterpret_cast<uint4*>(Wpk + (long)c * 4096 + m * 16);
#pragma unroll
    for (int t = 0; t < 4; t++)
        d[t] = make_uint4(hi[t], hi[t + 4], lo[t], lo[t + 4]);
}

// ===========================================================================
// pack_rows: [C][n] fp32 -> quad-packed (pairs across first dim) — feat only
// ===========================================================================
__global__ void __launch_bounds__(256)
pack_rows_kernel(const float* __restrict__ src, uint32_t* __restrict__ dst,
                 int chunks)
{
    const long idx = (long)blockIdx.x * 256 + threadIdx.x;
    const int  n   = (int)(idx & (HW - 1));
    const long bc  = idx >> 10;
    const int  c   = (int)(bc % chunks);
    const long b   = bc / chunks;

    const float* s = src + (b * chunks + c) * 16 * (long)HW + n;
    float f[16];
#pragma unroll
    for (int j = 0; j < 16; j++) f[j] = s[(long)j * HW];

    uint32_t hi[8], lo[8];
#pragma unroll
    for (int u = 0; u < 8; u++) {
        hi[u] = bf16x2_pack(f[2 * u], f[2 * u + 1]);
        lo[u] = bf16x2_residual(f[2 * u], f[2 * u + 1], hi[u]);
    }
    uint4* base = reinterpret_cast<uint4*>(dst + (b * chunks + c) * (long)(HW * 16) + n * 16);
#pragma unroll
    for (int t = 0; t < 4; t++)
        base[t] = make_uint4(hi[t], hi[t + 4], lo[t], lo[t + 4]);
}

// ===========================================================================
// prep_cam: camH = superchunk-32 fp16 copy of cam
// ===========================================================================
__global__ void __launch_bounds__(256)
prep_cam_kernel(const float* __restrict__ cam, __half* __restrict__ camH)
{
    const long i4 = (long)blockIdx.x * blockDim.x + threadIdx.x;
    const float4 v = reinterpret_cast<const float4*>(cam)[i4];
    const long row  = i4 >> 8;
    const int  idx4 = (int)(i4 & 255);
    const int  sc   = idx4 >> 3;
    const int  j    = idx4 & 7;
    const int p0 = 2 * j, p1 = 2 * j + 1;
    const int w0 = (p0 & 3) * 4 + (p0 >> 2);
    const int w1 = (p1 & 3) * 4 + (p1 >> 2);
    __half2* base = reinterpret_cast<__half2*>(camH + row * HW + sc * 32);
    base[w0] = __floats2half2_rn(v.x, v.y);
    base[w1] = __floats2half2_rn(v.z, v.w);
}

// ===========================================================================
// Softmax: fp32 row of 1024 -> fp16 16-chunk permuted, in-place (__expf)
// ===========================================================================
__global__ void __launch_bounds__(256)
softmax_kernel(float* __restrict__ P)
{
    __shared__ float red_m[8];
    __shared__ float red_s[8];

    const long row = blockIdx.x;
    float* rowp = P + row * (long)HW;
    const float4 v = reinterpret_cast<const float4*>(rowp)[threadIdx.x];

    const int lane = threadIdx.x & 31;
    const int warp = threadIdx.x >> 5;

    float m = fmaxf(fmaxf(v.x, v.y), fmaxf(v.z, v.w));
#pragma unroll
    for (int o = 16; o; o >>= 1) m = fmaxf(m, __shfl_xor_sync(0xffffffffu, m, o));
    if (lane == 0) red_m[warp] = m;
    __syncthreads();
    m = red_m[0];
#pragma unroll
    for (int i = 1; i < 8; i++) m = fmaxf(m, red_m[i]);

    float4 e;
    e.x = __expf(v.x - m);
    e.y = __expf(v.y - m);
    e.z = __expf(v.z - m);
    e.w = __expf(v.w - m);
    float s = e.x + e.y + e.z + e.w;
#pragma unroll
    for (int o = 16; o; o >>= 1) s += __shfl_xor_sync(0xffffffffu, s, o);
    if (lane == 0) red_s[warp] = s;
    __syncthreads();
    s = red_s[0];
#pragma unroll
    for (int i = 1; i < 8; i++) s += red_s[i];

    const float inv = 1.0f / s;
    const int chunk = threadIdx.x >> 2;
    const int j     = threadIdx.x & 3;
    const int slotA = ((2 * j) & 3) * 2 + ((2 * j) >> 2);
    const int slotB = ((2 * j + 1) & 3) * 2 + ((2 * j + 1) >> 2);
    __half2* base = reinterpret_cast<__half2*>(reinterpret_cast<__half*>(rowp) + chunk * 16);
    base[slotA] = __floats2half2_rn(e.x * inv, e.y * inv);
    base[slotB] = __floats2half2_rn(e.z * inv, e.w * inv);
}

// ===========================================================================
// Quad-packed 3xbf16 GEMM (two-barrier pipeline, round-15 structure).
//   ASTREAM=false (GEMM1): A staged in smem (stage = A 8KB + B 8KB).
//   ASTREAM=true  (GEMM2): A frags via __ldg from gmem; smem stages B only.
//   PACKOUT=true  (GEMM1): epilogue emits quad-packed bf16 hi/lo.
// ===========================================================================
#define T2_STAGES 4
#define T2_SMEM_FULL (T2_STAGES * 4096 * 4)   // 65536 (A+B staging)
#define T2_SMEM_BONLY (T2_STAGES * 2048 * 4)  // 32768 (B only)

template<int KCHUNKS, int CSA, int CSB, bool PACKOUT, bool ASTREAM>
__global__ void __launch_bounds__(256, 2)
pk_gemm_kernel(const uint32_t* __restrict__ Apk, const uint32_t* __restrict__ Bpk,
               float* __restrict__ Cg,
               long bsA, long bsB, long bsC)
{
    extern __shared__ uint32_t smu[];
    constexpr int STAGEU = ASTREAM ? 2048 : 4096;

    const int tid  = threadIdx.x;
    const int wid  = tid >> 5;
    const int lane = tid & 31;
    const int g    = lane >> 2;
    const int t    = lane & 3;
    const int wm   = wid >> 1;
    const int wn   = wid & 1;

    const int b  = blockIdx.z;
    const int m0 = blockIdx.y * 128;
    const int n0 = blockIdx.x * 128;

    const uint32_t sm_u = smem_u32(smu);

    uint32_t sOffB[2];
    const uint32_t* bPtr[2];
    uint32_t sOffA[2];
    const uint32_t* aPtr[2];
#pragma unroll
    for (int i = 0; i < 2; i++) {
        const int cid = tid + i * 256;
        const int row = cid >> 2, q = cid & 3;
        const uint32_t off = (uint32_t)(row * 16 + q * 4) * 4u;
        if (ASTREAM) {
            sOffB[i] = off;
        } else {
            sOffA[i] = off;
            sOffB[i] = off + 2048u * 4u;
            aPtr[i] = Apk + b * bsA + (long)(m0 + row) * 16 + q * 4;
        }
        bPtr[i] = Bpk + b * bsB + (long)(n0 + row) * 16 + q * 4;
    }

    const uint32_t* aFrag[2][2];
    if (ASTREAM) {
#pragma unroll
        for (int mt = 0; mt < 2; mt++)
#pragma unroll
            for (int r = 0; r < 2; r++)
                aFrag[mt][r] = Apk + b * bsA
                             + (long)(m0 + wm * 32 + mt * 16 + r * 8 + g) * 16 + t * 4;
    }

    float acc[2][8][4];
#pragma unroll
    for (int i = 0; i < 2; i++)
#pragma unroll
        for (int j = 0; j < 8; j++)
#pragma unroll
            for (int k = 0; k < 4; k++) acc[i][j][k] = 0.f;

    auto load_stage = [&](int s) {
        const uint32_t sa = sm_u + (uint32_t)(s * STAGEU) * 4u;
        if (!ASTREAM) {
#pragma unroll
            for (int i = 0; i < 2; i++) {
                CP_ASYNC16(sa + sOffA[i], aPtr[i]);
                aPtr[i] += CSA;
            }
        }
#pragma unroll
        for (int i = 0; i < 2; i++) {
            CP_ASYNC16(sa + sOffB[i], bPtr[i]);
            bPtr[i] += CSB;
        }
    };

#pragma unroll
    for (int s = 0; s < T2_STAGES - 1; s++) {
        load_stage(s);
        CP_COMMIT();
    }

    for (int it = 0; it < KCHUNKS; it++) {
        CP_WAIT2();
        __syncthreads();
        if (it + T2_STAGES - 1 < KCHUNKS)
            load_stage((it + T2_STAGES - 1) & (T2_STAGES - 1));
        CP_COMMIT();

        const int s = it & (T2_STAGES - 1);
        const uint32_t* sbase = smu + s * STAGEU;
        const uint32_t* sb = ASTREAM ? sbase : sbase + 2048;

        uint32_t ahi[2][4], alo[2][4];
        if (ASTREAM) {
#pragma unroll
            for (int mt = 0; mt < 2; mt++) {
                const uint4 v0 = __ldg(reinterpret_cast<const uint4*>(aFrag[mt][0] + (long)it * CSA));
                const uint4 v1 = __ldg(reinterpret_cast<const uint4*>(aFrag[mt][1] + (long)it * CSA));
                ahi[mt][0] = v0.x; ahi[mt][1] = v1.x; ahi[mt][2] = v0.y; ahi[mt][3] = v1.y;
                alo[mt][0] = v0.z; alo[mt][1] = v1.z; alo[mt][2] = v0.w; alo[mt][3] = v1.w;
            }
        } else {
            const uint32_t* sa = sbase;
#pragma unroll
            for (int mt = 0; mt < 2; mt++) {
                const int r0 = wm * 32 + mt * 16 + g;
                const uint4 v0 = *reinterpret_cast<const uint4*>(sa + r0 * 16 + t * 4);
                const uint4 v1 = *reinterpret_cast<const uint4*>(sa + (r0 + 8) * 16 + t * 4);
                ahi[mt][0] = v0.x; ahi[mt][1] = v1.x; ahi[mt][2] = v0.y; ahi[mt][3] = v1.y;
                alo[mt][0] = v0.z; alo[mt][1] = v1.z; alo[mt][2] = v0.w; alo[mt][3] = v1.w;
            }
        }

#pragma unroll
        for (int nt = 0; nt < 8; nt++) {
            const int n = wn * 64 + nt * 8 + g;
            const uint4 u = *reinterpret_cast<const uint4*>(sb + n * 16 + t * 4);
#pragma unroll
            for (int mt = 0; mt < 2; mt++) {
                mma_bf16(acc[mt][nt], ahi[mt], u.x, u.y);
                mma_bf16(acc[mt][nt], ahi[mt], u.z, u.w);
                mma_bf16(acc[mt][nt], alo[mt], u.x, u.y);
            }
        }
        __syncthreads();
    }

    if (PACKOUT) {
        uint32_t* Cpk = reinterpret_cast<uint32_t*>(Cg) + (long)b * bsC;
        const bool evn = (g & 1) == 0;
        const int  u   = g >> 1;
#pragma unroll
        for (int mt = 0; mt < 2; mt++) {
            const int chunk = (m0 >> 4) + wm * 2 + mt;
            uint32_t* dstC = Cpk + (long)chunk * (HW * 16);
#pragma unroll
            for (int nt = 0; nt < 8; nt++) {
                const int n = n0 + wn * 64 + nt * 8 + 2 * t;
                float v0 = acc[mt][nt][0], v1 = acc[mt][nt][1];
                float v2 = acc[mt][nt][2], v3 = acc[mt][nt][3];
                const float p0 = __shfl_xor_sync(0xffffffffu, v0, 4);
                const float p1 = __shfl_xor_sync(0xffffffffu, v1, 4);
                const float p2 = __shfl_xor_sync(0xffffffffu, v2, 4);
                const float p3 = __shfl_xor_sync(0xffffffffu, v3, 4);
                if (evn) {
                    uint2 w0, w1;
                    w0.x = bf16x2_pack(v0, p0);  w0.y = bf16x2_pack(v2, p2);
                    w1.x = bf16x2_pack(v1, p1);  w1.y = bf16x2_pack(v3, p3);
                    *reinterpret_cast<uint2*>(dstC + (long)n * 16 + u * 4) = w0;
                    *reinterpret_cast<uint2*>(dstC + (long)(n + 1) * 16 + u * 4) = w1;
                } else {
                    uint32_t h, l0, l2, l1, l3;
                    h = bf16x2_pack(p0, v0); l0 = bf16x2_residual(p0, v0, h);
                    h = bf16x2_pack(p2, v2); l2 = bf16x2_residual(p2, v2, h);
                    h = bf16x2_pack(p1, v1); l1 = bf16x2_residual(p1, v1, h);
                    h = bf16x2_pack(p3, v3); l3 = bf16x2_residual(p3, v3, h);
                    uint2 w0 = make_uint2(l0, l2);
                    uint2 w1 = make_uint2(l1, l3);
                    *reinterpret_cast<uint2*>(dstC + (long)n * 16 + u * 4 + 2) = w0;
                    *reinterpret_cast<uint2*>(dstC + (long)(n + 1) * 16 + u * 4 + 2) = w1;
                }
            }
        }
    } else {
        float* C = Cg + (long)b * bsC;
#pragma unroll
        for (int mt = 0; mt < 2; mt++) {
            const int mrow = m0 + wm * 32 + mt * 16 + g;
#pragma unroll
            for (int nt = 0; nt < 8; nt++) {
                const int n = n0 + wn * 64 + nt * 8 + 2 * t;
                *(float2*)(C + (long)mrow * HW + n) = make_float2(acc[mt][nt][0], acc[mt][nt][1]);
                *(float2*)(C + (long)(mrow + 8) * HW + n) = make_float2(acc[mt][nt][2], acc[mt][nt][3]);
            }
        }
    }
}

// ===========================================================================
// GEMM3 (fp16 m16n8k16): A (camH superchunk) streamed via LDG.128 + prefetch;
// smem stages B only. Two-barrier pipeline (round-15 structure).
// ===========================================================================
#define G3_STAGES 4
#define G3_CHUNK_BYTES 4096
#define G3_STAGE_BYTES (2 * G3_CHUNK_BYTES)
#define G3_SMEM_BYTES  (G3_STAGES * G3_STAGE_BYTES)   // 32768
#define G3_SCITER (HW / 32)

__global__ void __launch_bounds__(256, 2)
gemm3_f16_kernel(const __half* __restrict__ camH,
                 const float* __restrict__ Pf,
                 float* __restrict__ out, const float* __restrict__ alphap)
{
    extern __shared__ char smc[];

    const int tid  = threadIdx.x;
    const int wid  = tid >> 5;
    const int lane = tid & 31;
    const int g    = lane >> 2;
    const int t    = lane & 3;
    const int wm   = wid >> 1;
    const int wn   = wid & 1;

    const int b  = blockIdx.z;
    const int m0 = blockIdx.y * 128;
    const int n0 = blockIdx.x * 128;
    const __half* camHB = camH + (long)b * CCH * HW;

    const uint32_t sm_u = smem_u32(smc);

    uint32_t sOff[2];
    const __half* bPtr[2];
    {
        const __half* PBh = reinterpret_cast<const __half*>(Pf + (long)b * HW * HW);
#pragma unroll
        for (int i = 0; i < 2; i++) {
            const int c = tid + i * 256;
            const int row = c >> 2, q = c & 3;
            sOff[i] = (uint32_t)((q >> 1) * G3_CHUNK_BYTES + row * 32 + (q & 1) * 16);
            bPtr[i] = PBh + (long)(n0 + row) * 2048 + q * 8;
        }
    }

    const __half* aRow[2][2];
#pragma unroll
    for (int mt = 0; mt < 2; mt++)
#pragma unroll
        for (int r = 0; r < 2; r++)
            aRow[mt][r] = camHB + (long)(m0 + wm * 32 + mt * 16 + r * 8 + g) * HW + t * 8;

    float acc[2][8][4];
#pragma unroll
    for (int i = 0; i < 2; i++)
#pragma unroll
        for (int j = 0; j < 8; j++)
#pragma unroll
            for (int k = 0; k < 4; k++) acc[i][j][k] = 0.f;

    auto load_stage = [&](int s) {
        const uint32_t sb = sm_u + (uint32_t)(s * G3_STAGE_BYTES);
#pragma unroll
        for (int i = 0; i < 2; i++) {
            CP_ASYNC16(sb + sOff[i], bPtr[i]);
            bPtr[i] += 32;
        }
    };

#pragma unroll
    for (int s = 0; s < G3_STAGES - 1; s++) {
        load_stage(s);
        CP_COMMIT();
    }

    uint4 aC[2][2], aN[2][2];
#pragma unroll
    for (int mt = 0; mt < 2; mt++)
#pragma unroll
        for (int r = 0; r < 2; r++)
            aC[mt][r] = __ldg(reinterpret_cast<const uint4*>(aRow[mt][r]));

    for (int it = 0; it < G3_SCITER; it++) {
        CP_WAIT2();
        __syncthreads();
        if (it + G3_STAGES - 1 < G3_SCITER)
            load_stage((it + G3_STAGES - 1) & (G3_STAGES - 1));
        CP_COMMIT();

        if (it + 1 < G3_SCITER) {
#pragma unroll
            for (int mt = 0; mt < 2; mt++)
#pragma unroll
                for (int r = 0; r < 2; r++)
                    aN[mt][r] = __ldg(reinterpret_cast<const uint4*>(aRow[mt][r] + (it + 1) * 32));
        }

        const int s = it & (G3_STAGES - 1);
        const char* sb = smc + s * G3_STAGE_BYTES;

#pragma unroll
        for (int ch = 0; ch < 2; ch++) {
            const char* sbc = sb + ch * G3_CHUNK_BYTES;
            uint32_t a0[2], a1[2], a2[2], a3[2];
#pragma unroll
            for (int mt = 0; mt < 2; mt++) {
                if (ch == 0) {
                    a0[mt] = aC[mt][0].x; a1[mt] = aC[mt][1].x;
                    a2[mt] = aC[mt][0].y; a3[mt] = aC[mt][1].y;
                } else {
                    a0[mt] = aC[mt][0].z; a1[mt] = aC[mt][1].z;
                    a2[mt] = aC[mt][0].w; a3[mt] = aC[mt][1].w;
                }
            }
#pragma unroll
            for (int nt = 0; nt < 8; nt++) {
                const int n = wn * 64 + nt * 8 + g;
                const uint2 bf = *reinterpret_cast<const uint2*>(sbc + n * 32 + t * 8);
#pragma unroll
                for (int mt = 0; mt < 2; mt++)
                    mma_f16(acc[mt][nt], a0[mt], a1[mt], a2[mt], a3[mt], bf.x, bf.y);
            }
        }
        __syncthreads();

#pragma unroll
        for (int mt = 0; mt < 2; mt++)
#pragma unroll
            for (int r = 0; r < 2; r++)
                aC[mt][r] = aN[mt][r];
    }

    const float alpha = *alphap;
    float* outB = out + (long)b * CCH * HW;
#pragma unroll
    for (int mt = 0; mt < 2; mt++) {
        const int mrow = m0 + wm * 32 + mt * 16 + g;
        const __half* camRow0 = camHB + (long)mrow * HW;
        const __half* camRow1 = camHB + (long)(mrow + 8) * HW;
#pragma unroll
        for (int nt = 0; nt < 8; nt++) {
            const int n = n0 + wn * 64 + nt * 8 + 2 * t;
            const int p = (n >> 1) & 15;
            const int off = (n & ~31) + ((p & 3) * 4 + (p >> 2)) * 2;
            {
                const float2 cv = __half22float2(*reinterpret_cast<const __half2*>(camRow0 + off));
                float2 o;
                o.x = alpha * acc[mt][nt][0] + cv.x;
                o.y = alpha * acc[mt][nt][1] + cv.y;
                *(float2*)(outB + (long)mrow * HW + n) = o;
            }
            {
                const float2 cv = __half22float2(*reinterpret_cast<const __half2*>(camRow1 + off));
                float2 o;
                o.x = alpha * acc[mt][nt][2] + cv.x;
                o.y = alpha * acc[mt][nt][3] + cv.y;
                *(float2*)(outB + (long)(mrow + 8) * HW + n) = o;
            }
        }
    }
}

// ---------------------------------------------------------------------------
extern "C" void kernel_launch(void* const* d_in, const int* in_sizes, int n_in,
                              void* d_out, int out_size)
{
    const float* feat  = (const float*)d_in[0];
    const float* cam   = (const float*)d_in[1];
    const float* Wq    = (const float*)d_in[2];
    const float* Wk    = (const float*)d_in[3];
    const float* alpha = (const float*)d_in[4];
    float* out = (float*)d_out;

    float* P;
    __half* camH;
    uint32_t *Wpk, *featPk, *f12pk;
    cudaGetSymbolAddress((void**)&P, g_P);
    cudaGetSymbolAddress((void**)&camH, g_camH);
    cudaGetSymbolAddress((void**)&Wpk, g_Wpk);
    cudaGetSymbolAddress((void**)&featPk, g_featPk);
    cudaGetSymbolAddress((void**)&f12pk, g_f12pk);

    // Preps
    prep_w_kernel<<<128, 256>>>(Wq, Wk, Wpk);
    pack_rows_kernel<<<(unsigned)((long)BATCH * 128 * HW / 256), 256>>>(feat, featPk, 128);
    prep_cam_kernel<<<(unsigned)((long)BATCH * CCH * HW / 4 / 256), 256>>>(cam, camH);

    // GEMM1 (A smem, PACKOUT): f12pk = quad-packed W @ feat
    {
        cudaFuncSetAttribute((const void*)pk_gemm_kernel<128, 4096, 16384, true, false>,
                             cudaFuncAttributeMaxDynamicSharedMemorySize, T2_SMEM_FULL);
        dim3 grid(HW / 128, 256 / 128, BATCH);
        pk_gemm_kernel<128, 4096, 16384, true, false><<<grid, 256, T2_SMEM_FULL>>>(
            Wpk, featPk, (float*)f12pk,
            0L, (long)128 * HW * 16, (long)16 * HW * 16);
    }

    // GEMM2 (A streamed from gmem, B-only smem): S = f1^T f2 (8 chunks)
    {
        cudaFuncSetAttribute((const void*)pk_gemm_kernel<8, 16384, 16384, false, true>,
                             cudaFuncAttributeMaxDynamicSharedMemorySize, T2_SMEM_BONLY);
        dim3 grid(HW / 128, HW / 128, BATCH);
        pk_gemm_kernel<8, 16384, 16384, false, true><<<grid, 256, T2_SMEM_BONLY>>>(
            f12pk, f12pk + (long)8 * HW * 16, P,
            (long)16 * HW * 16, (long)16 * HW * 16, (long)HW * HW);
    }

    // Softmax (fp32 -> 16-chunk fp16, in-place)
    softmax_kernel<<<BATCH * HW, 256>>>(P);

    // GEMM3: out = alpha * cam @ P^T + cam
    {
        cudaFuncSetAttribute(gemm3_f16_kernel,
                             cudaFuncAttributeMaxDynamicSharedMemorySize, G3_SMEM_BYTES);
        dim3 grid(HW / 128, CCH / 128, BATCH);
        gemm3_f16_kernel<<<grid, 256, G3_SMEM_BYTES>>>(camH, P, out, alpha);
    }
}